// round 13
// baseline (speedup 1.0000x reference)
#include <cuda_runtime.h>

// Problem constants
#define NB   16        // batches
#define NPB  262144    // elements per batch (512*512)
#define HB   64        // histogram bins
#define HC   64        // hist CTAs per batch
#define HT   128       // hist threads per CTA
#define MC   64        // minmax CTAs per batch

#define KL_EPS 1e-8f
#define WEIGHT 0.1f

// ---------------- device scratch (no allocations allowed) ----------------
__device__ float g_pmin[NB][MC];
__device__ float g_pmax[NB][MC];
__device__ float g_part[NB][2][HC][HB];   // [batch][target=0/pred=1][cta][bin]

// ---------------- kernel 1: per-batch min/max partials (no atomics) ----------------
// grid (MC, NB) = 1024 CTAs x 256 threads -> 262144 threads, 4 float4 each.
// DRAM-bound by design (16MB read), enough outstanding loads to fill HBM.
__global__ void __launch_bounds__(256) k_minmax(const float* __restrict__ target) {
    const int b = blockIdx.y;
    const float4* base = reinterpret_cast<const float4*>(target)
                         + (size_t)b * (NPB / 4) + (size_t)blockIdx.x * (NPB / 4 / MC);
    float lo = __int_as_float(0x7f800000);   // +inf
    float hi = __int_as_float(0xff800000);   // -inf
    #pragma unroll
    for (int k = 0; k < (NPB / 4 / MC) / 256; k++) {
        float4 v = base[k * 256 + threadIdx.x];
        lo = fminf(lo, fminf(fminf(v.x, v.y), fminf(v.z, v.w)));
        hi = fmaxf(hi, fmaxf(fmaxf(v.x, v.y), fmaxf(v.z, v.w)));
    }
    #pragma unroll
    for (int o = 16; o; o >>= 1) {
        lo = fminf(lo, __shfl_xor_sync(0xffffffffu, lo, o));
        hi = fmaxf(hi, __shfl_xor_sync(0xffffffffu, hi, o));
    }
    __shared__ float slo[8], shi[8];
    int w = threadIdx.x >> 5;
    if ((threadIdx.x & 31) == 0) { slo[w] = lo; shi[w] = hi; }
    __syncthreads();
    if (threadIdx.x == 0) {
        #pragma unroll
        for (int k = 1; k < 8; k++) { lo = fminf(lo, slo[k]); hi = fmaxf(hi, shi[k]); }
        g_pmin[b][blockIdx.x] = lo;
        g_pmax[b][blockIdx.x] = hi;
    }
}

// ---------------- kernel 2: soft histograms ----------------
// Gaussian KDE, sigma = 1 bin, 13-bin truncated window (|d| <= 6.5).
// Truncation bias cancels between pred/target hists inside the KL (verified
// empirically R10-R12: 13/15/17-bin windows show no monotone rel_err trend);
// the true accuracy floor was fp32 rounding in the TAIL reductions, now fp64.
// CENTER-OUT recurrence seeded with precise expf at the max-weight center bin:
//   up:   g *= r,  r0 = exp(c - 0.5),  r *= e^-1
//   down: g *= q,  q0 = exp(-c - 0.5) = e^-1 / r0,  q *= e^-1
// Per-thread SMEM histograms hist[bin*HT + tid] -> bank-conflict-free, no atomics.
__global__ void __launch_bounds__(HT) k_hist(const float* __restrict__ pred,
                                             const float* __restrict__ target) {
    __shared__ float hist[HB * HT];   // 32 KB
    __shared__ float s_vmin, s_scale;
    const int b   = blockIdx.y;
    const int c0  = blockIdx.x;
    const int tid = threadIdx.x;
    const float EINV = 0.36787944117144233f;  // e^-1

    if (tid < 32) {
        float lo = fminf(g_pmin[b][tid], g_pmin[b][tid + 32]);
        float hi = fmaxf(g_pmax[b][tid], g_pmax[b][tid + 32]);
        #pragma unroll
        for (int o = 16; o; o >>= 1) {
            lo = fminf(lo, __shfl_xor_sync(0xffffffffu, lo, o));
            hi = fmaxf(hi, __shfl_xor_sync(0xffffffffu, hi, o));
        }
        if (tid == 0) {
            s_vmin  = lo;
            s_scale = 64.0f / (hi - lo + KL_EPS);
        }
    }

    #pragma unroll 1
    for (int phase = 0; phase < 2; phase++) {
        const float* src = (phase == 0) ? target : pred;
        const float4* base = reinterpret_cast<const float4*>(src)
                             + (size_t)b * (NPB / 4) + (size_t)c0 * (NPB / 4 / HC);

        #pragma unroll
        for (int j = 0; j < HB; j++) hist[j * HT + tid] = 0.0f;
        __syncthreads();

        const float vmin  = s_vmin;
        const float scale = s_scale;
        const float bias  = -vmin * scale;

        #pragma unroll 1
        for (int i = tid; i < NPB / 4 / HC; i += HT) {
            float4 v = base[i];
            float xs[4] = {v.x, v.y, v.z, v.w};
            #pragma unroll
            for (int e = 0; e < 4; e++) {
                float u  = fmaf(xs[e], scale, bias);   // position in bin units
                float jf = floorf(u);
                int   jc = (int)jf;                    // center bin (contains u)
                float c  = u - jf - 0.5f;              // offset from center bin's center
                float g0 = expf(-0.5f * c * c);
                float r  = expf(c - 0.5f);             // upward ratio seed
                float q  = __fdividef(EINV, r);        // exp(-c-0.5) = e^-1 / r

                if ((unsigned)jc < (unsigned)HB) hist[jc * HT + tid] += g0;
                float gu = g0, gd = g0;
                #pragma unroll
                for (int m = 1; m <= 6; m++) {
                    gu *= r;
                    int ju = jc + m;
                    if ((unsigned)ju < (unsigned)HB) hist[ju * HT + tid] += gu;
                    r *= EINV;
                    gd *= q;
                    int jd = jc - m;
                    if ((unsigned)jd < (unsigned)HB) hist[jd * HT + tid] += gd;
                    q *= EINV;
                }
            }
        }
        __syncthreads();

        // reduce 128 per-thread slices -> 64 bins (rotated, conflict-free).
        // fp32 with 4 split accumulators: per-bin rel error ~2e-8 (harmless).
        if (tid < HB) {
            const int bin = tid;
            float s0 = 0.f, s1 = 0.f, s2 = 0.f, s3 = 0.f;
            #pragma unroll 4
            for (int s = 0; s < HT; s += 4) {
                s0 += hist[bin * HT + ((s + 0 + bin) & (HT - 1))];
                s1 += hist[bin * HT + ((s + 1 + bin) & (HT - 1))];
                s2 += hist[bin * HT + ((s + 2 + bin) & (HT - 1))];
                s3 += hist[bin * HT + ((s + 3 + bin) & (HT - 1))];
            }
            g_part[b][phase][c0][bin] = (s0 + s1) + (s2 + s3);
        }
        __syncthreads();
    }
}

// ---------------- kernel 3: fused tail, FP64 (reduce + KL + output) ----------------
// Single CTA, 1024 threads = 32 warps. All cross-CTA sums, normalizations and
// logs in double: kills the fp32 rounding floor that the ~700x KL log-difference
// amplification turned into ~6e-4 final error. Fixed dataflow -> deterministic.
__global__ void __launch_bounds__(1024) k_tail(float* __restrict__ out) {
    __shared__ double hsum[NB][2][HB];   // 16 KB
    __shared__ double recp[NB][2];
    __shared__ double wsum[32];
    const int tid  = threadIdx.x;
    const int w    = tid >> 5;          // 0..31 -> (b,p)
    const int lane = tid & 31;
    const int wb   = w >> 1;
    const int wp   = w & 1;

    // stage 1: sum over HC cta-partials in double (coalesced fp32 loads)
    const float* src = &g_part[wb][wp][0][0];
    double s0 = 0.0, s1 = 0.0;
    #pragma unroll 8
    for (int c = 0; c < HC; c++) {
        s0 += (double)src[c * HB + lane];
        s1 += (double)src[c * HB + lane + 32];
    }
    hsum[wb][wp][lane]      = s0;
    hsum[wb][wp][lane + 32] = s1;

    // per-(b,p) total via warp butterfly (fixed dataflow)
    double tot = s0 + s1;
    #pragma unroll
    for (int o = 16; o; o >>= 1) tot += __shfl_xor_sync(0xffffffffu, tot, o);
    if (lane == 0) recp[wb][wp] = 1.0 / (tot + (double)KL_EPS);
    __syncthreads();

    // stage 2: KL terms, one per (batch, bin)
    const int b = tid >> 6;
    const int j = tid & (HB - 1);
    const double tp = hsum[b][0][j] * recp[b][0];
    const double pp = hsum[b][1][j] * recp[b][1];
    double term = tp * (log(tp + (double)KL_EPS) - log(pp + (double)KL_EPS));

    // stage 3: reduce 1024 terms (warp butterfly + cross-warp)
    #pragma unroll
    for (int o = 16; o; o >>= 1) term += __shfl_xor_sync(0xffffffffu, term, o);
    if (lane == 0) wsum[w] = term;
    __syncthreads();
    if (w == 0) {
        double v = wsum[lane];
        #pragma unroll
        for (int o = 16; o; o >>= 1) v += __shfl_xor_sync(0xffffffffu, v, o);
        if (lane == 0) out[0] = (float)((double)WEIGHT * (v / (double)NB));
    }
}

// ---------------- launch ----------------
extern "C" void kernel_launch(void* const* d_in, const int* in_sizes, int n_in,
                              void* d_out, int out_size) {
    const float* pred   = (const float*)d_in[0];
    const float* target = (const float*)d_in[1];
    float* out = (float*)d_out;

    k_minmax<<<dim3(MC, NB), 256>>>(target);
    k_hist  <<<dim3(HC, NB), HT>>>(pred, target);
    k_tail  <<<1, 1024>>>(out);
}

// round 14
// speedup vs baseline: 2.6595x; 2.6595x over previous
#include <cuda_runtime.h>

// Problem constants
#define NB   16        // batches
#define NPB  262144    // elements per batch (512*512)
#define HB   64        // histogram bins
#define HC   64        // hist CTAs per batch
#define HT   128       // hist threads per CTA
#define MC   32        // minmax CTAs per batch

#define KL_EPS 1e-8f
#define WEIGHT 0.1f

// ---------------- device scratch (no allocations allowed) ----------------
__device__ float g_pmin[NB][MC];
__device__ float g_pmax[NB][MC];
__device__ float g_part[NB][2][HC][HB];   // [batch][target=0/pred=1][cta][bin]

// ---------------- kernel 1: per-batch min/max partials (no atomics) ----------------
// grid (MC, NB) = 512 CTAs x 256 threads, 8 float4 each, fully unrolled -> MLP=8.
__global__ void __launch_bounds__(256) k_minmax(const float* __restrict__ target) {
    const int b = blockIdx.y;
    const float4* base = reinterpret_cast<const float4*>(target)
                         + (size_t)b * (NPB / 4) + (size_t)blockIdx.x * (NPB / 4 / MC);
    float lo = __int_as_float(0x7f800000);   // +inf
    float hi = __int_as_float(0xff800000);   // -inf
    #pragma unroll
    for (int k = 0; k < (NPB / 4 / MC) / 256; k++) {
        float4 v = base[k * 256 + threadIdx.x];
        lo = fminf(lo, fminf(fminf(v.x, v.y), fminf(v.z, v.w)));
        hi = fmaxf(hi, fmaxf(fmaxf(v.x, v.y), fmaxf(v.z, v.w)));
    }
    #pragma unroll
    for (int o = 16; o; o >>= 1) {
        lo = fminf(lo, __shfl_xor_sync(0xffffffffu, lo, o));
        hi = fmaxf(hi, __shfl_xor_sync(0xffffffffu, hi, o));
    }
    __shared__ float slo[8], shi[8];
    int w = threadIdx.x >> 5;
    if ((threadIdx.x & 31) == 0) { slo[w] = lo; shi[w] = hi; }
    __syncthreads();
    if (threadIdx.x == 0) {
        #pragma unroll
        for (int k = 1; k < 8; k++) { lo = fminf(lo, slo[k]); hi = fmaxf(hi, shi[k]); }
        g_pmin[b][blockIdx.x] = lo;
        g_pmax[b][blockIdx.x] = hi;
    }
}

// ---------------- kernel 2: soft histograms ----------------
// Gaussian KDE, sigma = 1 bin, 13-bin truncated window (|d| <= 6.5).
// __expf seeds (2-ulp): the error is a smooth symmetric function of the
// in-bin offset c, identical in distribution for pred/target -> first-order
// cancels in the normalized-hist KL (the R9->R10 error drop is attributable
// to recurrence direction, not expf precision).
// CENTER-OUT recurrence:
//   up:   g *= r,  r0 = exp(c - 0.5),  r *= e^-1
//   down: g *= q,  q0 = exp(-c - 0.5), q *= e^-1
// Per-thread SMEM histograms hist[bin*HT + tid] -> bank-conflict-free, no atomics.
__global__ void __launch_bounds__(HT) k_hist(const float* __restrict__ pred,
                                             const float* __restrict__ target) {
    __shared__ float hist[HB * HT];   // 32 KB
    __shared__ float s_vmin, s_scale;
    const int b   = blockIdx.y;
    const int c0  = blockIdx.x;
    const int tid = threadIdx.x;
    const float EINV = 0.36787944117144233f;  // e^-1

    if (tid < 32) {
        float lo = g_pmin[b][tid];
        float hi = g_pmax[b][tid];
        #pragma unroll
        for (int o = 16; o; o >>= 1) {
            lo = fminf(lo, __shfl_xor_sync(0xffffffffu, lo, o));
            hi = fmaxf(hi, __shfl_xor_sync(0xffffffffu, hi, o));
        }
        if (tid == 0) {
            s_vmin  = lo;
            s_scale = 64.0f / (hi - lo + KL_EPS);
        }
    }

    #pragma unroll 1
    for (int phase = 0; phase < 2; phase++) {
        const float* src = (phase == 0) ? target : pred;
        const float4* base = reinterpret_cast<const float4*>(src)
                             + (size_t)b * (NPB / 4) + (size_t)c0 * (NPB / 4 / HC);

        #pragma unroll
        for (int j = 0; j < HB; j++) hist[j * HT + tid] = 0.0f;
        __syncthreads();

        const float vmin  = s_vmin;
        const float scale = s_scale;
        const float bias  = -vmin * scale;

        #pragma unroll 1
        for (int i = tid; i < NPB / 4 / HC; i += HT) {
            float4 v = base[i];
            float xs[4] = {v.x, v.y, v.z, v.w};
            #pragma unroll
            for (int e = 0; e < 4; e++) {
                float u  = fmaf(xs[e], scale, bias);   // position in bin units
                float jf = floorf(u);
                int   jc = (int)jf;                    // center bin (contains u)
                float c  = u - jf - 0.5f;              // offset from center bin's center
                float g0 = __expf(-0.5f * c * c);
                float r  = __expf(c - 0.5f);           // upward ratio seed
                float q  = __expf(-c - 0.5f);          // downward ratio seed

                if ((unsigned)jc < (unsigned)HB) hist[jc * HT + tid] += g0;
                float gu = g0, gd = g0;
                #pragma unroll
                for (int m = 1; m <= 6; m++) {
                    gu *= r;
                    int ju = jc + m;
                    if ((unsigned)ju < (unsigned)HB) hist[ju * HT + tid] += gu;
                    r *= EINV;
                    gd *= q;
                    int jd = jc - m;
                    if ((unsigned)jd < (unsigned)HB) hist[jd * HT + tid] += gd;
                    q *= EINV;
                }
            }
        }
        __syncthreads();

        // reduce 128 per-thread slices -> 64 bins (rotated, conflict-free)
        if (tid < HB) {
            const int bin = tid;
            float s0 = 0.f, s1 = 0.f, s2 = 0.f, s3 = 0.f;
            #pragma unroll 4
            for (int s = 0; s < HT; s += 4) {
                s0 += hist[bin * HT + ((s + 0 + bin) & (HT - 1))];
                s1 += hist[bin * HT + ((s + 1 + bin) & (HT - 1))];
                s2 += hist[bin * HT + ((s + 2 + bin) & (HT - 1))];
                s3 += hist[bin * HT + ((s + 3 + bin) & (HT - 1))];
            }
            g_part[b][phase][c0][bin] = (s0 + s1) + (s2 + s3);
        }
        __syncthreads();
    }
}

// ---------------- kernel 3: fused tail (Kahan fp32 + float-float, 32 fp64 divides) ----------------
// Single CTA, 1024 threads = 32 warps, warp w -> (batch,phase).
// Accuracy design (R13 lesson: fp64 LOOPS on one SM cost ~90us; fp64 scalar ops are free):
//  - stage-1 bin sums: fp32 Kahan (s,c) pairs -> common-mode error ~1e-9.
//  - per-(b,p) totals: lane-0 Kahan over bins; ONLY the reciprocal is fp64
//    (its rounding is a common-mode scale over all bins -> KL-amplified),
//    split into (hi,lo) floats.
//  - per-bin prob: float-float product (s,c)x(hi,lo) via FMA two-product;
//    remaining roundings are per-bin independent -> average out (~4e-5 final).
// Fixed dataflow everywhere -> deterministic.
__global__ void __launch_bounds__(1024) k_tail(float* __restrict__ out) {
    __shared__ float hs[NB][2][HB];     // Kahan sum
    __shared__ float hc[NB][2][HB];     // Kahan compensation
    __shared__ float rhi[NB][2], rlo[NB][2];
    __shared__ float wsum[32];
    const int tid  = threadIdx.x;
    const int w    = tid >> 5;          // 0..31 -> (b,p)
    const int lane = tid & 31;
    const int wb   = w >> 1;
    const int wp   = w & 1;

    // stage 1: Kahan-sum 64 CTA partials for bins `lane` and `lane+32`
    const float* src = &g_part[wb][wp][0][0];
    float s0 = 0.f, k0 = 0.f, s1 = 0.f, k1 = 0.f;
    #pragma unroll 4
    for (int c = 0; c < HC; c++) {
        float a0 = src[c * HB + lane];
        float y0 = a0 - k0; float t0 = s0 + y0; k0 = (t0 - s0) - y0; s0 = t0;
        float a1 = src[c * HB + lane + 32];
        float y1 = a1 - k1; float t1 = s1 + y1; k1 = (t1 - s1) - y1; s1 = t1;
    }
    hs[wb][wp][lane] = s0;      hc[wb][wp][lane] = k0;
    hs[wb][wp][lane + 32] = s1; hc[wb][wp][lane + 32] = k1;
    __syncwarp();

    // per-(b,p) total: lane-0 Kahan over 64 bins, fp64 reciprocal (32 divides total)
    if (lane == 0) {
        float S = 0.f, K = 0.f;
        #pragma unroll 4
        for (int j = 0; j < HB; j++) {
            float a = hs[wb][wp][j] + hc[wb][wp][j];
            float y = a - K; float t = S + y; K = (t - S) - y; S = t;
        }
        double rd = 1.0 / ((double)S + (double)K + (double)KL_EPS);
        float hi = (float)rd;
        rhi[wb][wp] = hi;
        rlo[wb][wp] = (float)(rd - (double)hi);
    }
    __syncthreads();

    // stage 2: KL term per (batch, bin) with float-float products
    const int b = tid >> 6;
    const int j = tid & (HB - 1);

    float sT = hs[b][0][j], cT = hc[b][0][j];
    float sP = hs[b][1][j], cP = hc[b][1][j];
    float rT = rhi[b][0], rTl = rlo[b][0];
    float rP = rhi[b][1], rPl = rlo[b][1];

    // tp = (sT + cT) * (rT + rTl), double-float via FMA two-product
    float tph = sT * rT;
    float tpl = fmaf(sT, rT, -tph) + (cT * rT + sT * rTl);
    float pph = sP * rP;
    float ppl = fmaf(sP, rP, -pph) + (cP * rP + sP * rPl);

    float tpf  = tph + tpl;
    float argT = tph + (tpl + KL_EPS);
    float argP = pph + (ppl + KL_EPS);
    float term = tpf * (logf(argT) - logf(argP));

    // stage 3: reduce 1024 terms (warp butterfly + cross-warp)
    #pragma unroll
    for (int o = 16; o; o >>= 1) term += __shfl_xor_sync(0xffffffffu, term, o);
    if (lane == 0) wsum[w] = term;
    __syncthreads();
    if (w == 0) {
        float v = wsum[lane];
        #pragma unroll
        for (int o = 16; o; o >>= 1) v += __shfl_xor_sync(0xffffffffu, v, o);
        if (lane == 0) out[0] = WEIGHT * (v / (float)NB);
    }
}

// ---------------- launch ----------------
extern "C" void kernel_launch(void* const* d_in, const int* in_sizes, int n_in,
                              void* d_out, int out_size) {
    const float* pred   = (const float*)d_in[0];
    const float* target = (const float*)d_in[1];
    float* out = (float*)d_out;

    k_minmax<<<dim3(MC, NB), 256>>>(target);
    k_hist  <<<dim3(HC, NB), HT>>>(pred, target);
    k_tail  <<<1, 1024>>>(out);
}

// round 15
// speedup vs baseline: 2.7649x; 1.0396x over previous
#include <cuda_runtime.h>

// Problem constants
#define NB   16        // batches
#define NPB  262144    // elements per batch (512*512)
#define HB   64        // histogram bins
#define HC   32        // fused CTAs per batch (grid 512 -- co-residency guaranteed)
#define HT   128       // threads per CTA
#define NP2  (HB / 2)  // 32 float2 bin-pairs

#define KL_EPS 1e-8f
#define WEIGHT 0.1f

// ---------------- device scratch (no allocations allowed) ----------------
__device__ float g_pmin[NB][HC];
__device__ float g_pmax[NB][HC];
__device__ float g_part[NB][2][HC][HB];   // [batch][target=0/pred=1][cta][bin]
__device__ unsigned int g_bar;            // monotonic grid-barrier counter (never reset;
                                          // each launch adds exactly NB*HC arrivals, so
                                          // gen = old/512 is launch-local -> replay-safe)

// ---------------- fused kernel: minmax + grid barrier + soft histograms ----------
// Residency proof (grid barrier REQUIRES all 512 CTAs co-resident):
//   smem = 32.8KB -> <=6 CTAs/SM; __launch_bounds__(128,4) caps regs at 128
//   -> >=4 CTAs/SM by registers. floor = 4 CTAs/SM * 148 SM = 592 >= 512. OK.
//
// Hot loop: Gaussian KDE, sigma = 1 bin. Window = 14 slots aligned to an even
// base = (jc-6)&~1 -> 7 float2 pair-updates (LDS.64/STS.64). Worst-case covered
// half-width is 5.5 bins on each side -- IDENTICAL to the previous 13-bin
// window, so truncation behavior is unchanged (rel_err floor ~2e-4).
// Seed at slot 6 (d = u - base - 6.5 in [-0.5, 1.5)), recur outward:
//   up:   s7 = s6*r, r *= e^-1, ...     r0 = exp(d - 0.5)
//   down: s5 = s6*q, q *= e^-1, ...     q0 = exp(-d - 0.5)
// Per-thread pair-histograms hist[pair*HT + tid] -> conflict-free (pair stride
// 1024B is bank-neutral), no atomics.
__global__ void __launch_bounds__(HT, 4) k_fused(const float* __restrict__ pred,
                                                 const float* __restrict__ target) {
    __shared__ float2 hist[NP2 * HT];   // 32 KB
    __shared__ float slo[4], shi[4];
    __shared__ float s_vmin, s_scale;
    const int b   = blockIdx.y;
    const int c0  = blockIdx.x;
    const int tid = threadIdx.x;
    const float EINV = 0.36787944117144233f;  // e^-1

    // ---- phase A: min/max of this CTA's own target slice (8192 elements) ----
    const float4* tbase = reinterpret_cast<const float4*>(target)
                          + (size_t)b * (NPB / 4) + (size_t)c0 * (NPB / 4 / HC);
    {
        float lo = __int_as_float(0x7f800000);   // +inf
        float hi = __int_as_float(0xff800000);   // -inf
        #pragma unroll
        for (int k = 0; k < (NPB / 4 / HC) / HT; k++) {   // 16 float4 per thread
            float4 v = tbase[k * HT + tid];
            lo = fminf(lo, fminf(fminf(v.x, v.y), fminf(v.z, v.w)));
            hi = fmaxf(hi, fmaxf(fmaxf(v.x, v.y), fmaxf(v.z, v.w)));
        }
        #pragma unroll
        for (int o = 16; o; o >>= 1) {
            lo = fminf(lo, __shfl_xor_sync(0xffffffffu, lo, o));
            hi = fmaxf(hi, __shfl_xor_sync(0xffffffffu, hi, o));
        }
        int w = tid >> 5;
        if ((tid & 31) == 0) { slo[w] = lo; shi[w] = hi; }
        __syncthreads();
        if (tid == 0) {
            lo = fminf(fminf(slo[0], slo[1]), fminf(slo[2], slo[3]));
            hi = fmaxf(fmaxf(shi[0], shi[1]), fmaxf(shi[2], shi[3]));
            g_pmin[b][c0] = lo;
            g_pmax[b][c0] = hi;
            __threadfence();   // publish partials before arriving
        }
    }

    // ---- grid barrier (monotonic counter, replay-safe) ----
    if (tid == 0) {
        unsigned int old = atomicAdd(&g_bar, 1u);
        unsigned int tgt = (old / (NB * HC) + 1u) * (NB * HC);
        while (*(volatile unsigned int*)&g_bar < tgt) { }
        __threadfence();
    }
    __syncthreads();

    // ---- global vmin/scale for this batch (HC=32 partials, warp 0) ----
    if (tid < 32) {
        float lo = *((volatile float*)&g_pmin[b][tid]);
        float hi = *((volatile float*)&g_pmax[b][tid]);
        #pragma unroll
        for (int o = 16; o; o >>= 1) {
            lo = fminf(lo, __shfl_xor_sync(0xffffffffu, lo, o));
            hi = fmaxf(hi, __shfl_xor_sync(0xffffffffu, hi, o));
        }
        if (tid == 0) {
            s_vmin  = lo;
            s_scale = 64.0f / (hi - lo + KL_EPS);
        }
    }
    __syncthreads();

    const float vmin  = s_vmin;
    const float scale = s_scale;
    const float bias  = -vmin * scale;

    // ---- phase B: soft histograms (target then pred) ----
    #pragma unroll 1
    for (int phase = 0; phase < 2; phase++) {
        const float4* base4 = (phase == 0)
            ? tbase
            : reinterpret_cast<const float4*>(pred)
              + (size_t)b * (NPB / 4) + (size_t)c0 * (NPB / 4 / HC);

        #pragma unroll
        for (int i = tid; i < NP2 * HT; i += HT) hist[i] = make_float2(0.f, 0.f);
        __syncthreads();

        #pragma unroll 1
        for (int i = tid; i < NPB / 4 / HC; i += HT) {
            float4 v = base4[i];
            float xs[4] = {v.x, v.y, v.z, v.w};
            #pragma unroll
            for (int e = 0; e < 4; e++) {
                float u  = fmaf(xs[e], scale, bias);   // position in bin units
                int   jc = (int)floorf(u);             // center bin
                int   bb = (jc - 6) & ~1;              // even window base
                int   pb = bb >> 1;                    // pair base (may be <0, guarded)
                float d  = u - (float)bb - 6.5f;       // in [-0.5, 1.5)
                float g6 = __expf(-0.5f * d * d);
                float r  = __expf(d - 0.5f);
                float q  = __expf(-d - 0.5f);

                float2* hp = &hist[pb * HT + tid];     // pointer formed, deref guarded

                // up chain: slots 6..13 -> pairs 3,4,5,6
                float s6 = g6, s7 = s6 * r; r *= EINV;
                if ((unsigned)(pb + 3) < (unsigned)NP2) {
                    float2 h = hp[3 * HT]; h.x += s6; h.y += s7; hp[3 * HT] = h;
                }
                float s8 = s7 * r; r *= EINV; float s9 = s8 * r; r *= EINV;
                if ((unsigned)(pb + 4) < (unsigned)NP2) {
                    float2 h = hp[4 * HT]; h.x += s8; h.y += s9; hp[4 * HT] = h;
                }
                float s10 = s9 * r; r *= EINV; float s11 = s10 * r; r *= EINV;
                if ((unsigned)(pb + 5) < (unsigned)NP2) {
                    float2 h = hp[5 * HT]; h.x += s10; h.y += s11; hp[5 * HT] = h;
                }
                float s12 = s11 * r; r *= EINV; float s13 = s12 * r;
                if ((unsigned)(pb + 6) < (unsigned)NP2) {
                    float2 h = hp[6 * HT]; h.x += s12; h.y += s13; hp[6 * HT] = h;
                }
                // down chain: slots 5..0 -> pairs 2,1,0
                float s5 = g6 * q; q *= EINV; float s4 = s5 * q; q *= EINV;
                if ((unsigned)(pb + 2) < (unsigned)NP2) {
                    float2 h = hp[2 * HT]; h.x += s4; h.y += s5; hp[2 * HT] = h;
                }
                float s3 = s4 * q; q *= EINV; float s2 = s3 * q; q *= EINV;
                if ((unsigned)(pb + 1) < (unsigned)NP2) {
                    float2 h = hp[1 * HT]; h.x += s2; h.y += s3; hp[1 * HT] = h;
                }
                float s1 = s2 * q; q *= EINV; float s0 = s1 * q;
                if ((unsigned)pb < (unsigned)NP2) {
                    float2 h = hp[0]; h.x += s0; h.y += s1; hp[0] = h;
                }
            }
        }
        __syncthreads();

        // reduce 128 per-thread slices -> 64 bins (warp 0, rotated float2 loads)
        if (tid < NP2) {
            const int p = tid;
            float sx = 0.f, sy = 0.f;
            #pragma unroll 8
            for (int s = 0; s < HT; s++) {
                float2 h = hist[p * HT + ((s + p) & (HT - 1))];
                sx += h.x; sy += h.y;
            }
            g_part[b][phase][c0][2 * p]     = sx;
            g_part[b][phase][c0][2 * p + 1] = sy;
        }
        __syncthreads();
    }
}

// ---------------- tail kernel (Kahan fp32 + float-float, 32 fp64 divides) ----------
__global__ void __launch_bounds__(1024) k_tail(float* __restrict__ out) {
    __shared__ float hs[NB][2][HB];     // Kahan sum
    __shared__ float hc[NB][2][HB];     // Kahan compensation
    __shared__ float rhi[NB][2], rlo[NB][2];
    __shared__ float wsum[32];
    const int tid  = threadIdx.x;
    const int w    = tid >> 5;          // 0..31 -> (b,p)
    const int lane = tid & 31;
    const int wb   = w >> 1;
    const int wp   = w & 1;

    // stage 1: Kahan-sum HC cta-partials for bins `lane` and `lane+32`
    const float* src = &g_part[wb][wp][0][0];
    float s0 = 0.f, k0 = 0.f, s1 = 0.f, k1 = 0.f;
    #pragma unroll 4
    for (int c = 0; c < HC; c++) {
        float a0 = src[c * HB + lane];
        float y0 = a0 - k0; float t0 = s0 + y0; k0 = (t0 - s0) - y0; s0 = t0;
        float a1 = src[c * HB + lane + 32];
        float y1 = a1 - k1; float t1 = s1 + y1; k1 = (t1 - s1) - y1; s1 = t1;
    }
    hs[wb][wp][lane] = s0;      hc[wb][wp][lane] = k0;
    hs[wb][wp][lane + 32] = s1; hc[wb][wp][lane + 32] = k1;
    __syncwarp();

    // per-(b,p) total: lane-0 Kahan over 64 bins, fp64 reciprocal (32 divides total)
    if (lane == 0) {
        float S = 0.f, K = 0.f;
        #pragma unroll 4
        for (int j = 0; j < HB; j++) {
            float a = hs[wb][wp][j] + hc[wb][wp][j];
            float y = a - K; float t = S + y; K = (t - S) - y; S = t;
        }
        double rd = 1.0 / ((double)S + (double)K + (double)KL_EPS);
        float hi = (float)rd;
        rhi[wb][wp] = hi;
        rlo[wb][wp] = (float)(rd - (double)hi);
    }
    __syncthreads();

    // stage 2: KL term per (batch, bin) with float-float products
    const int b = tid >> 6;
    const int j = tid & (HB - 1);

    float sT = hs[b][0][j], cT = hc[b][0][j];
    float sP = hs[b][1][j], cP = hc[b][1][j];
    float rT = rhi[b][0], rTl = rlo[b][0];
    float rP = rhi[b][1], rPl = rlo[b][1];

    float tph = sT * rT;
    float tpl = fmaf(sT, rT, -tph) + (cT * rT + sT * rTl);
    float pph = sP * rP;
    float ppl = fmaf(sP, rP, -pph) + (cP * rP + sP * rPl);

    float tpf  = tph + tpl;
    float argT = tph + (tpl + KL_EPS);
    float argP = pph + (ppl + KL_EPS);
    float term = tpf * (logf(argT) - logf(argP));

    // stage 3: reduce 1024 terms (warp butterfly + cross-warp)
    #pragma unroll
    for (int o = 16; o; o >>= 1) term += __shfl_xor_sync(0xffffffffu, term, o);
    if (lane == 0) wsum[w] = term;
    __syncthreads();
    if (w == 0) {
        float v = wsum[lane];
        #pragma unroll
        for (int o = 16; o; o >>= 1) v += __shfl_xor_sync(0xffffffffu, v, o);
        if (lane == 0) out[0] = WEIGHT * (v / (float)NB);
    }
}

// ---------------- launch ----------------
extern "C" void kernel_launch(void* const* d_in, const int* in_sizes, int n_in,
                              void* d_out, int out_size) {
    const float* pred   = (const float*)d_in[0];
    const float* target = (const float*)d_in[1];
    float* out = (float*)d_out;

    k_fused<<<dim3(HC, NB), HT>>>(pred, target);
    k_tail <<<1, 1024>>>(out);
}